// round 12
// baseline (speedup 1.0000x reference)
#include <cuda_runtime.h>
#include <cuda_fp16.h>
#include <math.h>
#include <stdint.h>

// Problem constants
#define BB 2
#define NN 2048
#define DD 1024
#define HH 16
#define HDIM 64
#define MM (BB*NN)   // 4096

// q pre-scale: (1/sqrt(64)) * log2(e)  -> softmax computed with exp2
#define SCALE_LOG2 0.18033688011112042f
#define ONES_H2 0x3C003C00u

#define PO_S (1024*4096)   // per-split stride of o-partials
#define PL_S (1024*64)

// ---------------------------------------------------------------------------
// Device scratch
// ---------------------------------------------------------------------------
__device__ __half g_xh [MM*DD];
__device__ __half g_wh [4*DD*DD];   // weights fp16, ORIGINAL [k][n] layout
__device__ __half g_qh [BB*HH*NN*HDIM];  // pre-scaled by SCALE_LOG2
__device__ __half g_kh [BB*HH*NN*HDIM];
__device__ __half g_vh [BB*HH*NN*HDIM];
__device__ __half g_ch [MM*DD];     // ctx fp16
__device__ float  g_po [2*PO_S];    // attention o-partials (unnormalized)
__device__ float  g_pl [2*PL_S];    // row sums per partial
__device__ float  g_pm [2*PL_S];    // fixed reference per partial row

// ---------------------------------------------------------------------------
// PTX helpers (compute_103-safe: no 'a' features)
// ---------------------------------------------------------------------------
__device__ __forceinline__ uint32_t smem_u32(const void* p) {
    uint32_t a;
    asm("{ .reg .u64 t; cvta.to.shared.u64 t, %1; cvt.u32.u64 %0, t; }"
        : "=r"(a) : "l"(p));
    return a;
}
__device__ __forceinline__ void cp16(uint32_t dst, const void* src) {
    asm volatile("cp.async.cg.shared.global [%0], [%1], 16;" :: "r"(dst), "l"(src));
}
#define CP_COMMIT() asm volatile("cp.async.commit_group;")
#define CP_WAIT(n)  asm volatile("cp.async.wait_group %0;" :: "n"(n))

#define LDSM4(r, addr) \
    asm volatile("ldmatrix.sync.aligned.m8n8.x4.shared.b16 {%0,%1,%2,%3}, [%4];" \
        : "=r"((r)[0]), "=r"((r)[1]), "=r"((r)[2]), "=r"((r)[3]) : "r"(addr))
#define LDSM4T(r, addr) \
    asm volatile("ldmatrix.sync.aligned.m8n8.x4.trans.shared.b16 {%0,%1,%2,%3}, [%4];" \
        : "=r"((r)[0]), "=r"((r)[1]), "=r"((r)[2]), "=r"((r)[3]) : "r"(addr))

__device__ __forceinline__ void mma16816(float* d, const uint32_t* a,
                                         uint32_t b0, uint32_t b1) {
    asm volatile("mma.sync.aligned.m16n8k16.row.col.f32.f16.f16.f32 "
                 "{%0,%1,%2,%3}, {%4,%5,%6,%7}, {%8,%9}, {%0,%1,%2,%3};"
                 : "+f"(d[0]), "+f"(d[1]), "+f"(d[2]), "+f"(d[3])
                 : "r"(a[0]), "r"(a[1]), "r"(a[2]), "r"(a[3]), "r"(b0), "r"(b1));
}
__device__ __forceinline__ uint32_t pack_h2(float lo, float hi) {
    uint32_t r;
    asm("cvt.rn.f16x2.f32 %0, %1, %2;" : "=r"(r) : "f"(hi), "f"(lo));
    return r;
}
__device__ __forceinline__ uint32_t h2exp2(uint32_t x) {
    uint32_t y;
    asm("ex2.approx.f16x2 %0, %1;" : "=r"(y) : "r"(x));
    return y;
}

// ---------------------------------------------------------------------------
// Prep: all fp32 -> fp16 converts in one launch.
// blocks [0,4096): x;  [4096, 8192): weights (1024 blocks per matrix).
// ---------------------------------------------------------------------------
__global__ void convert_all_kernel(const float* __restrict__ x,
                                   const float* __restrict__ Wq,
                                   const float* __restrict__ Wk,
                                   const float* __restrict__ Wv,
                                   const float* __restrict__ Wo)
{
    int bid = blockIdx.x;
    const float* src;
    __half* dst;
    int i;
    if (bid < 4096) {
        src = x; dst = g_xh;
        i = bid * 256 + threadIdx.x;
    } else {
        int t = bid - 4096;
        int mat = t >> 10;
        src = (mat == 0) ? Wq : (mat == 1) ? Wk : (mat == 2) ? Wv : Wo;
        dst = g_wh + (size_t)mat * DD * DD;
        i = (t & 1023) * 256 + threadIdx.x;
    }
    float4 v = reinterpret_cast<const float4*>(src)[i];
    reinterpret_cast<__half2*>(dst)[i * 2]     = __floats2half2_rn(v.x, v.y);
    reinterpret_cast<__half2*>(dst)[i * 2 + 1] = __floats2half2_rn(v.z, v.w);
}

// ---------------------------------------------------------------------------
// HMMA fp16 GEMM: C[128x128] tile, BK=64, 3-stage cp.async pipeline.
// B = W in ORIGINAL [k][n] layout; B fragments via ldmatrix.trans.
// mode 0/1/2 -> g_qh/g_kh/g_vh head-split fp16; mode 3 -> fp32 out + bias.
// smem: 3 x (A 16KB | B 16KB) = 96KB dynamic.
// ---------------------------------------------------------------------------
#define GEMM_SMEM (3 * 32768)

__global__ void __launch_bounds__(256, 2)
gemm_hmma_kernel(const __half* __restrict__ A,
                 const float* __restrict__ bias,
                 float* __restrict__ outp,
                 int mode_base)
{
    extern __shared__ __align__(16) char gsm[];
    const uint32_t uS = smem_u32(gsm);

    const int tid  = threadIdx.x;
    const int wid  = tid >> 5;
    const int lane = tid & 31;
    const int mode = mode_base + blockIdx.z;
    const int m0 = blockIdx.y * 128;
    const int n0 = blockIdx.x * 128;

    const __half* __restrict__ Ap = A + (size_t)m0 * DD;
    const __half* __restrict__ Bp = g_wh + (size_t)mode * DD * DD + n0;

    const int wm = (wid & 3) * 32;
    const int wn = (wid >> 2) * 64;

    float acc[2][8][4];
    #pragma unroll
    for (int i = 0; i < 2; i++)
        #pragma unroll
        for (int j = 0; j < 8; j++)
            #pragma unroll
            for (int q = 0; q < 4; q++) acc[i][j][q] = 0.f;

    #define LOAD_STAGE(k0v, buf) do { \
        _Pragma("unroll") \
        for (int i = 0; i < 4; i++) { \
            int idx = i * 256 + tid; \
            int ra = idx >> 3, ca = idx & 7; \
            cp16(uS + (buf) * 32768 + ra * 128 + ((ca ^ (ra & 7)) * 16), \
                 Ap + (size_t)ra * DD + (k0v) + ca * 8); \
            int rb = idx >> 4, qb = idx & 15; \
            int hb = qb >> 3, cb = qb & 7; \
            cp16(uS + (buf) * 32768 + 16384 + hb * 8192 + rb * 128 + ((cb ^ (rb & 7)) * 16), \
                 Bp + (size_t)((k0v) + rb) * DD + hb * 64 + cb * 8); \
        } } while (0)

    LOAD_STAGE(0, 0);  CP_COMMIT();
    LOAD_STAGE(64, 1); CP_COMMIT();

    const int NS = DD / 64;   // 16 stages
    for (int s = 0; s < NS; s++) {
        const int buf = s % 3;
        if (s + 2 < NS) {
            LOAD_STAGE((s + 2) * 64, (s + 2) % 3);
            CP_COMMIT();
            CP_WAIT(2);
        } else if (s + 1 < NS) {
            CP_WAIT(1);
        } else {
            CP_WAIT(0);
        }
        __syncthreads();

        const uint32_t bA  = uS + buf * 32768;
        const uint32_t bBh = bA + 16384 + (wid >> 2) * 8192;

        #pragma unroll
        for (int ks = 0; ks < 4; ks++) {
            uint32_t af[2][4];
            #pragma unroll
            for (int mt = 0; mt < 2; mt++) {
                int row = wm + mt * 16 + (lane & 15);
                int c = ks * 2 + (lane >> 4);
                LDSM4(af[mt], bA + row * 128 + ((c ^ (row & 7)) * 16));
            }
            #pragma unroll
            for (int np = 0; np < 4; np++) {
                uint32_t bf[4];
                int rowb = ks * 16 + ((lane >> 3) & 1) * 8 + (lane & 7);
                int ccb  = 2 * np + (lane >> 4);
                LDSM4T(bf, bBh + rowb * 128 + ((ccb ^ (rowb & 7)) * 16));
                #pragma unroll
                for (int mt = 0; mt < 2; mt++) {
                    mma16816(acc[mt][np * 2],     af[mt], bf[0], bf[1]);
                    mma16816(acc[mt][np * 2 + 1], af[mt], bf[2], bf[3]);
                }
            }
        }
        __syncthreads();
    }
    #undef LOAD_STAGE

    if (mode < 3) {
        const float scale = (mode == 0) ? SCALE_LOG2 : 1.0f;
        __half* __restrict__ dst = (mode == 0) ? g_qh : (mode == 1) ? g_kh : g_vh;
        #pragma unroll
        for (int mt = 0; mt < 2; mt++) {
            int r = m0 + wm + mt * 16 + (lane >> 2);
            int bbv = r >> 11, seq = r & 2047;
            #pragma unroll
            for (int nt = 0; nt < 8; nt++) {
                int col = n0 + wn + nt * 8 + (lane & 3) * 2;
                int hh = col >> 6, hd = col & 63;
                size_t o = ((size_t)(bbv * HH + hh) * NN + seq) * HDIM + hd;
                *reinterpret_cast<__half2*>(dst + o) =
                    __floats2half2_rn(acc[mt][nt][0] * scale, acc[mt][nt][1] * scale);
                *reinterpret_cast<__half2*>(dst + o + 8 * HDIM) =
                    __floats2half2_rn(acc[mt][nt][2] * scale, acc[mt][nt][3] * scale);
            }
        }
    } else {
        #pragma unroll
        for (int mt = 0; mt < 2; mt++) {
            int r = m0 + wm + mt * 16 + (lane >> 2);
            #pragma unroll
            for (int nt = 0; nt < 8; nt++) {
                int col = n0 + wn + nt * 8 + (lane & 3) * 2;
                float b0 = bias[col], b1 = bias[col + 1];
                *reinterpret_cast<float2*>(outp + (size_t)r * DD + col) =
                    make_float2(acc[mt][nt][0] + b0, acc[mt][nt][1] + b1);
                *reinterpret_cast<float2*>(outp + (size_t)(r + 8) * DD + col) =
                    make_float2(acc[mt][nt][2] + b0, acc[mt][nt][3] + b1);
            }
        }
    }
}

// ---------------------------------------------------------------------------
// Split-K HMMA flash attention. grid (16, 16, 4): z -> (bb = z>>1, sp = z&1).
// CTA (i, sp) handles Q-tiles {31-i, i}; per qtile nk=qt+1 key tiles are split:
//   sp=0: tiles [nk-half .. nk-1] (diag side; first tile masked, sets m^)
//   sp=1: tiles [0 .. nk-half-1]  (no mask; m^ from its own first tile)
// Fixed-reference softmax per partial; partials (o fp32, l, m^) to gmem.
// Single barrier per iter; prefetch -> compute -> wait -> bar (race-free).
// smem: Q 8KB | K 2x8KB | V 2x8KB = 40KB. 128 threads, 5 CTAs/SM target.
// ---------------------------------------------------------------------------
#define ATTN_SMEM (40960)

__global__ void __launch_bounds__(128, 5) attn_hmma_kernel()
{
    extern __shared__ __align__(16) char dsm[];
    const uint32_t uQ = smem_u32(dsm);
    const uint32_t uK = uQ + 8192;
    const uint32_t uV = uK + 16384;

    const int tid  = threadIdx.x;
    const int wid  = tid >> 5;     // 0..3
    const int lane = tid & 31;
    const int h  = blockIdx.y;
    const int bb = blockIdx.z >> 1;
    const int sp = blockIdx.z & 1;
    const int wr0 = wid * 16;

    const __half* __restrict__ kp = g_kh + ((size_t)(bb * HH + h) * NN) * HDIM;
    const __half* __restrict__ vp = g_vh + ((size_t)(bb * HH + h) * NN) * HDIM;

    const float slope2 = exp2f(-0.5f * (float)(h + 1)) * SCALE_LOG2;
    const float s8 = slope2 * 8.f;

    #define LOAD_KV(t, buf) do { \
        const __half* ksrc = kp + (size_t)(t) * 64 * HDIM; \
        const __half* vsrc = vp + (size_t)(t) * 64 * HDIM; \
        _Pragma("unroll") \
        for (int i = 0; i < 4; i++) { \
            int idx = i * 128 + tid; \
            int r = idx >> 3, c = idx & 7; \
            uint32_t so = (buf) * 8192 + r * 128 + ((c ^ (r & 7)) * 16); \
            cp16(uK + so, ksrc + (size_t)r * HDIM + c * 8); \
            cp16(uV + so, vsrc + (size_t)r * HDIM + c * 8); \
        } } while (0)

    for (int phase = 0; phase < 2; phase++) {
        const int qt = (phase == 0) ? (31 - blockIdx.x) : blockIdx.x;
        const int nk = qt + 1;
        const int half = (nk + 1) >> 1;
        const int first_kt = (sp == 0) ? (nk - 1) : (nk - half - 1);
        const int count    = (sp == 0) ? half : (nk - half);
        const int r0l = wr0 + (lane >> 2);
        const int r1l = r0l + 8;
        const size_t qg = (size_t)((bb * HH + h) * 32 + qt);

        if (count == 0) {        // empty partial (sp==1, qt==0)
            if ((lane & 3) == 0) {
                g_pl[sp * PL_S + qg * 64 + r0l] = 0.f;
                g_pl[sp * PL_S + qg * 64 + r1l] = 0.f;
                g_pm[sp * PL_S + qg * 64 + r0l] = -1e30f;
                g_pm[sp * PL_S + qg * 64 + r1l] = -1e30f;
            }
            continue;
        }

        const int r0g = qt * 64 + r0l;   // global rows (for diag mask)
        const int r1g = r0g + 8;

        const __half* __restrict__ qp =
            g_qh + ((size_t)(bb * HH + h) * NN + qt * 64) * HDIM;

        // stage Q tile + first KV tile
        #pragma unroll
        for (int i = 0; i < 4; i++) {
            int idx = i * 128 + tid;
            int r = idx >> 3, c = idx & 7;
            cp16(uQ + r * 128 + ((c ^ (r & 7)) * 16), qp + (size_t)r * HDIM + c * 8);
        }
        CP_COMMIT();
        LOAD_KV(first_kt, 0);
        CP_COMMIT();
        CP_WAIT(0);
        __syncthreads();

        float m0 = 0.f, m1 = 0.f;
        float lacc[4] = {0.f, 0.f, 0.f, 0.f};
        float o[8][4];
        #pragma unroll
        for (int nb = 0; nb < 8; nb++)
            #pragma unroll
            for (int j = 0; j < 4; j++) o[nb][j] = 0.f;

        for (int it = 0; it < count; it++) {
            const int kt  = first_kt - it;
            const int buf = it & 1;

            // prefetch next tile (overwrites buffer of tile it-1; safe: last
            // read of that buffer was before the end-of-(it-1) barrier)
            if (it + 1 < count) {
                LOAD_KV(kt - 1, buf ^ 1);
                CP_COMMIT();
            }

            // Q fragments for this tile (reloaded; saves registers)
            uint32_t qf[4][4];
            #pragma unroll
            for (int ks = 0; ks < 4; ks++) {
                int row = wr0 + (lane & 15);
                int cq = 2 * ks + (lane >> 4);
                LDSM4(qf[ks], uQ + row * 128 + ((cq ^ (row & 7)) * 16));
            }

            // S = q~ . K^T
            const uint32_t bK = uK + buf * 8192;
            float c[8][4];
            #pragma unroll
            for (int nb = 0; nb < 8; nb++)
                #pragma unroll
                for (int j = 0; j < 4; j++) c[nb][j] = 0.f;
            #pragma unroll
            for (int ks = 0; ks < 4; ks++) {
                #pragma unroll
                for (int np = 0; np < 4; np++) {
                    uint32_t bf[4];
                    int row = np * 16 + (lane & 7) + ((lane >> 4) << 3);
                    int cc = 2 * ks + ((lane >> 3) & 1);
                    LDSM4(bf, bK + row * 128 + ((cc ^ (row & 7)) * 16));
                    mma16816(c[2 * np],     qf[ks], bf[0], bf[1]);
                    mma16816(c[2 * np + 1], qf[ks], bf[2], bf[3]);
                }
            }

            // softmax -> fp16 P fragments
            uint32_t ph[4][4];
            if (it == 0) {
                // first tile: alibi add (mask only if sp==0, i.e. diagonal),
                // then per-row max -> fixed reference m^ for this partial
                float mx0 = -1e30f, mx1 = -1e30f;
                #pragma unroll
                for (int nb = 0; nb < 8; nb++) {
                    int col = kt * 64 + nb * 8 + (lane & 3) * 2;
                    float t = slope2 * (float)col;
                    if (sp == 0) {
                        c[nb][0] = (col     > r0g) ? -1e30f : c[nb][0] + t;
                        c[nb][1] = (col + 1 > r0g) ? -1e30f : c[nb][1] + t + slope2;
                        c[nb][2] = (col     > r1g) ? -1e30f : c[nb][2] + t;
                        c[nb][3] = (col + 1 > r1g) ? -1e30f : c[nb][3] + t + slope2;
                    } else {
                        c[nb][0] += t;
                        c[nb][1] += t + slope2;
                        c[nb][2] += t;
                        c[nb][3] += t + slope2;
                    }
                    mx0 = fmaxf(mx0, fmaxf(c[nb][0], c[nb][1]));
                    mx1 = fmaxf(mx1, fmaxf(c[nb][2], c[nb][3]));
                }
                mx0 = fmaxf(mx0, __shfl_xor_sync(0xffffffffu, mx0, 1));
                mx0 = fmaxf(mx0, __shfl_xor_sync(0xffffffffu, mx0, 2));
                mx1 = fmaxf(mx1, __shfl_xor_sync(0xffffffffu, mx1, 1));
                mx1 = fmaxf(mx1, __shfl_xor_sync(0xffffffffu, mx1, 2));
                m0 = mx0;
                m1 = mx1;
                #pragma unroll
                for (int nb = 0; nb < 8; nb++) {
                    uint32_t pa = pack_h2(c[nb][0] - m0, c[nb][1] - m0);
                    uint32_t pb = pack_h2(c[nb][2] - m1, c[nb][3] - m1);
                    ph[nb >> 1][(nb & 1) * 2]     = h2exp2(pa);
                    ph[nb >> 1][(nb & 1) * 2 + 1] = h2exp2(pb);
                }
            } else {
                // steady state: p = exp2(s + alibi - m^); no max, no rescale
                float tb0 = fmaf(slope2, (float)(kt * 64 + (lane & 3) * 2), -m0);
                float tb1 = tb0 + (m0 - m1);
                #pragma unroll
                for (int nb = 0; nb < 8; nb++) {
                    float t0 = fmaf((float)nb, s8, tb0);
                    float t1 = fmaf((float)nb, s8, tb1);
                    uint32_t pa = pack_h2(c[nb][0] + t0, c[nb][1] + t0 + slope2);
                    uint32_t pb = pack_h2(c[nb][2] + t1, c[nb][3] + t1 + slope2);
                    ph[nb >> 1][(nb & 1) * 2]     = h2exp2(pa);
                    ph[nb >> 1][(nb & 1) * 2 + 1] = h2exp2(pb);
                }
            }

            // l += P.1 (ones-MMA) and O += P.V
            const uint32_t bV = uV + buf * 8192;
            #pragma unroll
            for (int kpi = 0; kpi < 4; kpi++) {
                mma16816(lacc, ph[kpi], ONES_H2, ONES_H2);
                #pragma unroll
                for (int np = 0; np < 4; np++) {
                    uint32_t vf[4];
                    int row = kpi * 16 + ((lane >> 3) & 1) * 8 + (lane & 7);
                    int cc = 2 * np + (lane >> 4);
                    LDSM4T(vf, bV + row * 128 + ((cc ^ (row & 7)) * 16));
                    mma16816(o[2 * np],     ph[kpi], vf[0], vf[1]);
                    mma16816(o[2 * np + 1], ph[kpi], vf[2], vf[3]);
                }
            }

            if (it + 1 < count) CP_WAIT(0);   // next tile landed (full overlap)
            __syncthreads();                  // all warps done with buf
        }

        // store partials (raw o, l, m^)
        float* __restrict__ po = g_po + (size_t)sp * PO_S + qg * 4096;
        #pragma unroll
        for (int nb = 0; nb < 8; nb++) {
            int col = nb * 8 + (lane & 3) * 2;
            *reinterpret_cast<float2*>(po + r0l * 64 + col) =
                make_float2(o[nb][0], o[nb][1]);
            *reinterpret_cast<float2*>(po + r1l * 64 + col) =
                make_float2(o[nb][2], o[nb][3]);
        }
        if ((lane & 3) == 0) {
            g_pl[sp * PL_S + qg * 64 + r0l] = lacc[0];
            g_pl[sp * PL_S + qg * 64 + r1l] = lacc[2];
            g_pm[sp * PL_S + qg * 64 + r0l] = m0;
            g_pm[sp * PL_S + qg * 64 + r1l] = m1;
        }
    }
    #undef LOAD_KV
}

// ---------------------------------------------------------------------------
// Combine partials -> normalized fp16 ctx. grid 1024, block 256.
// ---------------------------------------------------------------------------
__global__ void __launch_bounds__(256) combine_kernel()
{
    const int qg  = blockIdx.x;
    const int row = threadIdx.x >> 2;
    const int q4  = threadIdx.x & 3;

    const float ma = g_pm[qg * 64 + row];
    const float mb = g_pm[PL_S + qg * 64 + row];
    const float M  = fmaxf(ma, mb);
    float sa = exp2f(ma - M);
    float sb = exp2f(mb - M);
    const float l = g_pl[qg * 64 + row] * sa + g_pl[PL_S + qg * 64 + row] * sb;
    const float inv = 1.f / l;
    sa *= inv;
    sb *= inv;

    const int bbc = qg >> 9;
    const int hc  = (qg >> 5) & 15;
    const int qtc = qg & 31;

    const float* __restrict__ p0 = g_po + (size_t)qg * 4096 + row * 64 + q4 * 16;
    const float* __restrict__ p1 = p0 + PO_S;
    __half* __restrict__ dst =
        g_ch + ((size_t)(bbc * NN + qtc * 64 + row)) * DD + hc * 64 + q4 * 16;

    #pragma unroll
    for (int j = 0; j < 4; j++) {
        float4 x0 = *reinterpret_cast<const float4*>(p0 + j * 4);
        float4 x1 = *reinterpret_cast<const float4*>(p1 + j * 4);
        *reinterpret_cast<__half2*>(dst + j * 4) =
            __floats2half2_rn(x0.x * sa + x1.x * sb, x0.y * sa + x1.y * sb);
        *reinterpret_cast<__half2*>(dst + j * 4 + 2) =
            __floats2half2_rn(x0.z * sa + x1.z * sb, x0.w * sa + x1.w * sb);
    }
}

// ---------------------------------------------------------------------------
extern "C" void kernel_launch(void* const* d_in, const int* in_sizes, int n_in,
                              void* d_out, int out_size)
{
    const float* x  = (const float*)d_in[0];
    const float* Wq = (const float*)d_in[1];
    const float* Wk = (const float*)d_in[2];
    const float* Wv = (const float*)d_in[3];
    const float* Wo = (const float*)d_in[4];
    const float* bo = (const float*)d_in[5];
    float* out = (float*)d_out;

    cudaFuncSetAttribute(gemm_hmma_kernel,
                         cudaFuncAttributeMaxDynamicSharedMemorySize, GEMM_SMEM);
    cudaFuncSetAttribute(attn_hmma_kernel,
                         cudaFuncAttributeMaxDynamicSharedMemorySize, ATTN_SMEM);

    __half *xh, *ch;
    cudaGetSymbolAddress((void**)&xh, g_xh);
    cudaGetSymbolAddress((void**)&ch, g_ch);

    convert_all_kernel<<<8192, 256>>>(x, Wq, Wk, Wv, Wo);

    // QKV projections
    gemm_hmma_kernel<<<dim3(8, 32, 3), 256, GEMM_SMEM>>>(xh, nullptr, nullptr, 0);

    // attention: split-K x2, balanced pairing, fixed-reference softmax
    attn_hmma_kernel<<<dim3(16, HH, 2 * BB), 128, ATTN_SMEM>>>();

    // combine partials -> ctx fp16
    combine_kernel<<<1024, 256>>>();

    // output projection
    gemm_hmma_kernel<<<dim3(8, 32, 1), 256, GEMM_SMEM>>>(ch, bo, out, 3);
}

// round 13
// speedup vs baseline: 1.1067x; 1.1067x over previous
#include <cuda_runtime.h>
#include <cuda_fp16.h>
#include <math.h>
#include <stdint.h>

// Problem constants
#define BB 2
#define NN 2048
#define DD 1024
#define HH 16
#define HDIM 64
#define MM (BB*NN)   // 4096

// q pre-scale: (1/sqrt(64)) * log2(e)  -> softmax computed with exp2
#define SCALE_LOG2 0.18033688011112042f

// ---------------------------------------------------------------------------
// Device scratch
// ---------------------------------------------------------------------------
__device__ __half g_xh [MM*DD];
__device__ __half g_wh [4*DD*DD];   // weights fp16, ORIGINAL [k][n] layout
__device__ __half g_qh [BB*HH*NN*HDIM];  // pre-scaled by SCALE_LOG2
__device__ __half g_kh [BB*HH*NN*HDIM];
__device__ __half g_vh [BB*HH*NN*HDIM];
__device__ __half g_ch [MM*DD];     // ctx fp16

// ---------------------------------------------------------------------------
// PTX helpers (compute_103-safe: no 'a' features)
// ---------------------------------------------------------------------------
__device__ __forceinline__ uint32_t smem_u32(const void* p) {
    uint32_t a;
    asm("{ .reg .u64 t; cvta.to.shared.u64 t, %1; cvt.u32.u64 %0, t; }"
        : "=r"(a) : "l"(p));
    return a;
}
__device__ __forceinline__ void cp16(uint32_t dst, const void* src) {
    asm volatile("cp.async.cg.shared.global [%0], [%1], 16;" :: "r"(dst), "l"(src));
}
#define CP_COMMIT() asm volatile("cp.async.commit_group;")
#define CP_WAIT(n)  asm volatile("cp.async.wait_group %0;" :: "n"(n))

#define LDSM4(r, addr) \
    asm volatile("ldmatrix.sync.aligned.m8n8.x4.shared.b16 {%0,%1,%2,%3}, [%4];" \
        : "=r"((r)[0]), "=r"((r)[1]), "=r"((r)[2]), "=r"((r)[3]) : "r"(addr))
#define LDSM4T(r, addr) \
    asm volatile("ldmatrix.sync.aligned.m8n8.x4.trans.shared.b16 {%0,%1,%2,%3}, [%4];" \
        : "=r"((r)[0]), "=r"((r)[1]), "=r"((r)[2]), "=r"((r)[3]) : "r"(addr))

__device__ __forceinline__ void mma16816(float* d, const uint32_t* a,
                                         uint32_t b0, uint32_t b1) {
    asm volatile("mma.sync.aligned.m16n8k16.row.col.f32.f16.f16.f32 "
                 "{%0,%1,%2,%3}, {%4,%5,%6,%7}, {%8,%9}, {%0,%1,%2,%3};"
                 : "+f"(d[0]), "+f"(d[1]), "+f"(d[2]), "+f"(d[3])
                 : "r"(a[0]), "r"(a[1]), "r"(a[2]), "r"(a[3]), "r"(b0), "r"(b1));
}
__device__ __forceinline__ uint32_t pack_h2(float lo, float hi) {
    uint32_t r;
    asm("cvt.rn.f16x2.f32 %0, %1, %2;" : "=r"(r) : "f"(hi), "f"(lo));
    return r;
}
__device__ __forceinline__ uint32_t h2exp2(uint32_t x) {
    uint32_t y;
    asm("ex2.approx.f16x2 %0, %1;" : "=r"(y) : "r"(x));
    return y;
}
__device__ __forceinline__ uint32_t hadd2u(uint32_t a, uint32_t b) {
    uint32_t r;
    asm("add.f16x2 %0, %1, %2;" : "=r"(r) : "r"(a), "r"(b));
    return r;
}
__device__ __forceinline__ float h2sum(uint32_t v) {
    __half2 h = *reinterpret_cast<__half2*>(&v);
    return __half2float(__low2half(h)) + __half2float(__high2half(h));
}

// ---------------------------------------------------------------------------
// Prep: all fp32 -> fp16 converts in one launch.
// blocks [0,4096): x;  [4096, 8192): weights (1024 blocks per matrix).
// ---------------------------------------------------------------------------
__global__ void convert_all_kernel(const float* __restrict__ x,
                                   const float* __restrict__ Wq,
                                   const float* __restrict__ Wk,
                                   const float* __restrict__ Wv,
                                   const float* __restrict__ Wo)
{
    int bid = blockIdx.x;
    const float* src;
    __half* dst;
    int i;
    if (bid < 4096) {
        src = x; dst = g_xh;
        i = bid * 256 + threadIdx.x;
    } else {
        int t = bid - 4096;
        int mat = t >> 10;
        src = (mat == 0) ? Wq : (mat == 1) ? Wk : (mat == 2) ? Wv : Wo;
        dst = g_wh + (size_t)mat * DD * DD;
        i = (t & 1023) * 256 + threadIdx.x;
    }
    float4 v = reinterpret_cast<const float4*>(src)[i];
    reinterpret_cast<__half2*>(dst)[i * 2]     = __floats2half2_rn(v.x, v.y);
    reinterpret_cast<__half2*>(dst)[i * 2 + 1] = __floats2half2_rn(v.z, v.w);
}

// ---------------------------------------------------------------------------
// HMMA fp16 GEMM: C[128x128] tile, BK=64, 3-stage cp.async pipeline.
// B = W in ORIGINAL [k][n] layout; B fragments via ldmatrix.trans.
// mode 0/1/2 -> g_qh/g_kh/g_vh head-split fp16; mode 3 -> fp32 out + bias.
// smem: 3 x (A 16KB | B 16KB) = 96KB dynamic.
// ---------------------------------------------------------------------------
#define GEMM_SMEM (3 * 32768)

__global__ void __launch_bounds__(256, 2)
gemm_hmma_kernel(const __half* __restrict__ A,
                 const float* __restrict__ bias,
                 float* __restrict__ outp,
                 int mode_base)
{
    extern __shared__ __align__(16) char gsm[];
    const uint32_t uS = smem_u32(gsm);

    const int tid  = threadIdx.x;
    const int wid  = tid >> 5;
    const int lane = tid & 31;
    const int mode = mode_base + blockIdx.z;
    const int m0 = blockIdx.y * 128;
    const int n0 = blockIdx.x * 128;

    const __half* __restrict__ Ap = A + (size_t)m0 * DD;
    const __half* __restrict__ Bp = g_wh + (size_t)mode * DD * DD + n0;

    const int wm = (wid & 3) * 32;
    const int wn = (wid >> 2) * 64;

    float acc[2][8][4];
    #pragma unroll
    for (int i = 0; i < 2; i++)
        #pragma unroll
        for (int j = 0; j < 8; j++)
            #pragma unroll
            for (int q = 0; q < 4; q++) acc[i][j][q] = 0.f;

    #define LOAD_STAGE(k0v, buf) do { \
        _Pragma("unroll") \
        for (int i = 0; i < 4; i++) { \
            int idx = i * 256 + tid; \
            int ra = idx >> 3, ca = idx & 7; \
            cp16(uS + (buf) * 32768 + ra * 128 + ((ca ^ (ra & 7)) * 16), \
                 Ap + (size_t)ra * DD + (k0v) + ca * 8); \
            int rb = idx >> 4, qb = idx & 15; \
            int hb = qb >> 3, cb = qb & 7; \
            cp16(uS + (buf) * 32768 + 16384 + hb * 8192 + rb * 128 + ((cb ^ (rb & 7)) * 16), \
                 Bp + (size_t)((k0v) + rb) * DD + hb * 64 + cb * 8); \
        } } while (0)

    LOAD_STAGE(0, 0);  CP_COMMIT();
    LOAD_STAGE(64, 1); CP_COMMIT();

    const int NS = DD / 64;   // 16 stages
    for (int s = 0; s < NS; s++) {
        const int buf = s % 3;
        if (s + 2 < NS) {
            LOAD_STAGE((s + 2) * 64, (s + 2) % 3);
            CP_COMMIT();
            CP_WAIT(2);
        } else if (s + 1 < NS) {
            CP_WAIT(1);
        } else {
            CP_WAIT(0);
        }
        __syncthreads();

        const uint32_t bA  = uS + buf * 32768;
        const uint32_t bBh = bA + 16384 + (wid >> 2) * 8192;

        #pragma unroll
        for (int ks = 0; ks < 4; ks++) {
            uint32_t af[2][4];
            #pragma unroll
            for (int mt = 0; mt < 2; mt++) {
                int row = wm + mt * 16 + (lane & 15);
                int c = ks * 2 + (lane >> 4);
                LDSM4(af[mt], bA + row * 128 + ((c ^ (row & 7)) * 16));
            }
            #pragma unroll
            for (int np = 0; np < 4; np++) {
                uint32_t bf[4];
                int rowb = ks * 16 + ((lane >> 3) & 1) * 8 + (lane & 7);
                int ccb  = 2 * np + (lane >> 4);
                LDSM4T(bf, bBh + rowb * 128 + ((ccb ^ (rowb & 7)) * 16));
                #pragma unroll
                for (int mt = 0; mt < 2; mt++) {
                    mma16816(acc[mt][np * 2],     af[mt], bf[0], bf[1]);
                    mma16816(acc[mt][np * 2 + 1], af[mt], bf[2], bf[3]);
                }
            }
        }
        __syncthreads();
    }
    #undef LOAD_STAGE

    if (mode < 3) {
        const float scale = (mode == 0) ? SCALE_LOG2 : 1.0f;
        __half* __restrict__ dst = (mode == 0) ? g_qh : (mode == 1) ? g_kh : g_vh;
        #pragma unroll
        for (int mt = 0; mt < 2; mt++) {
            int r = m0 + wm + mt * 16 + (lane >> 2);
            int bbv = r >> 11, seq = r & 2047;
            #pragma unroll
            for (int nt = 0; nt < 8; nt++) {
                int col = n0 + wn + nt * 8 + (lane & 3) * 2;
                int hh = col >> 6, hd = col & 63;
                size_t o = ((size_t)(bbv * HH + hh) * NN + seq) * HDIM + hd;
                *reinterpret_cast<__half2*>(dst + o) =
                    __floats2half2_rn(acc[mt][nt][0] * scale, acc[mt][nt][1] * scale);
                *reinterpret_cast<__half2*>(dst + o + 8 * HDIM) =
                    __floats2half2_rn(acc[mt][nt][2] * scale, acc[mt][nt][3] * scale);
            }
        }
    } else {
        #pragma unroll
        for (int mt = 0; mt < 2; mt++) {
            int r = m0 + wm + mt * 16 + (lane >> 2);
            #pragma unroll
            for (int nt = 0; nt < 8; nt++) {
                int col = n0 + wn + nt * 8 + (lane & 3) * 2;
                float b0 = bias[col], b1 = bias[col + 1];
                *reinterpret_cast<float2*>(outp + (size_t)r * DD + col) =
                    make_float2(acc[mt][nt][0] + b0, acc[mt][nt][1] + b1);
                *reinterpret_cast<float2*>(outp + (size_t)(r + 8) * DD + col) =
                    make_float2(acc[mt][nt][2] + b0, acc[mt][nt][3] + b1);
            }
        }
    }
}

// ---------------------------------------------------------------------------
// HMMA flash attention (round-10 structure, best measured):
// balanced pairing (CTA i: Q-tiles {31-i, i}); reverse key order; fixed
// softmax reference m^ from the diagonal tile (no max tracking / no rescale).
// l row-sum via add.f16x2 on the fma pipe (frees 4 ones-MMAs/tile from the
// tensor pipe); 2-shfl reduce once per phase.
// dynamic smem: Q 8KB | K 2x8KB | V 2x8KB = 40KB. grid (16,16,2), 128 thr.
// ---------------------------------------------------------------------------
#define ATTN_SMEM (40960)

__global__ void __launch_bounds__(128, 4) attn_hmma_kernel()
{
    extern __shared__ __align__(16) char dsm[];
    const uint32_t uQ = smem_u32(dsm);
    const uint32_t uK = uQ + 8192;
    const uint32_t uV = uK + 16384;

    const int tid  = threadIdx.x;
    const int wid  = tid >> 5;     // 0..3
    const int lane = tid & 31;
    const int h  = blockIdx.y;
    const int bb = blockIdx.z;
    const int wr0 = wid * 16;

    const __half* __restrict__ kp = g_kh + ((size_t)(bb * HH + h) * NN) * HDIM;
    const __half* __restrict__ vp = g_vh + ((size_t)(bb * HH + h) * NN) * HDIM;

    const float slope2 = exp2f(-0.5f * (float)(h + 1)) * SCALE_LOG2;

    // alibi column constants (local part), qt-independent
    float a0[8];
    #pragma unroll
    for (int nb = 0; nb < 8; nb++)
        a0[nb] = slope2 * (float)(nb * 8 + (lane & 3) * 2);

    #define LOAD_KV(t, buf) do { \
        const __half* ksrc = kp + (size_t)(t) * 64 * HDIM; \
        const __half* vsrc = vp + (size_t)(t) * 64 * HDIM; \
        _Pragma("unroll") \
        for (int i = 0; i < 4; i++) { \
            int idx = i * 128 + tid; \
            int r = idx >> 3, c = idx & 7; \
            uint32_t so = (buf) * 8192 + r * 128 + ((c ^ (r & 7)) * 16); \
            cp16(uK + so, ksrc + (size_t)r * HDIM + c * 8); \
            cp16(uV + so, vsrc + (size_t)r * HDIM + c * 8); \
        } } while (0)

    for (int phase = 0; phase < 2; phase++) {
        const int qt = (phase == 0) ? (31 - blockIdx.x) : blockIdx.x;
        const int q0 = qt * 64;
        const int nkt = qt + 1;           // key tiles; processed nkt-1 .. 0
        const int r0 = q0 + wr0 + (lane >> 2);
        const int r1 = r0 + 8;

        const __half* __restrict__ qp =
            g_qh + ((size_t)(bb * HH + h) * NN + q0) * HDIM;

        // stage Q tile (64 x 64 fp16)
        #pragma unroll
        for (int i = 0; i < 4; i++) {
            int idx = i * 128 + tid;
            int r = idx >> 3, c = idx & 7;
            cp16(uQ + r * 128 + ((c ^ (r & 7)) * 16), qp + (size_t)r * HDIM + c * 8);
        }
        CP_COMMIT();
        LOAD_KV(nkt - 1, 0); CP_COMMIT();
        CP_WAIT(1);            // Q resident
        __syncthreads();

        // Q fragments, register-resident for this phase
        uint32_t qf[4][4];
        #pragma unroll
        for (int ks = 0; ks < 4; ks++) {
            int row = wr0 + (lane & 15);
            int c = 2 * ks + (lane >> 4);
            LDSM4(qf[ks], uQ + row * 128 + ((c ^ (row & 7)) * 16));
        }

        float m0 = 0.f, m1 = 0.f;   // fixed reference, set on diagonal tile
        float l0 = 0.f, l1 = 0.f;   // fp32 row-sum accumulators (per-thread)
        float o[8][4];
        #pragma unroll
        for (int nb = 0; nb < 8; nb++)
            #pragma unroll
            for (int j = 0; j < 4; j++) o[nb][j] = 0.f;

        for (int it = 0; it < nkt; it++) {
            const int kt  = nkt - 1 - it;
            const int buf = it & 1;
            if (it + 1 < nkt) {
                LOAD_KV(nkt - 2 - it, (it + 1) & 1);
                CP_COMMIT();
                CP_WAIT(1);
            } else {
                CP_WAIT(0);
            }
            __syncthreads();

            const uint32_t bK = uK + buf * 8192;
            const uint32_t bV = uV + buf * 8192;

            // S = q~ . K^T
            float c[8][4];
            #pragma unroll
            for (int nb = 0; nb < 8; nb++)
                #pragma unroll
                for (int j = 0; j < 4; j++) c[nb][j] = 0.f;

            #pragma unroll
            for (int ks = 0; ks < 4; ks++) {
                #pragma unroll
                for (int np = 0; np < 4; np++) {
                    uint32_t bf[4];
                    int row = np * 16 + (lane & 7) + ((lane >> 4) << 3);
                    int cc = 2 * ks + ((lane >> 3) & 1);
                    LDSM4(bf, bK + row * 128 + ((cc ^ (row & 7)) * 16));
                    mma16816(c[2 * np],     qf[ks], bf[0], bf[1]);
                    mma16816(c[2 * np + 1], qf[ks], bf[2], bf[3]);
                }
            }

            uint32_t ph[4][4];
            const float kadd = slope2 * (float)(kt * 64);
            if (it == 0) {
                // diagonal tile: mask + alibi, compute the fixed reference m^
                float mx0 = -1e30f, mx1 = -1e30f;
                #pragma unroll
                for (int nb = 0; nb < 8; nb++) {
                    int col = kt * 64 + nb * 8 + (lane & 3) * 2;
                    float t = a0[nb] + kadd;
                    c[nb][0] = (col     > r0) ? -1e30f : c[nb][0] + t;
                    c[nb][1] = (col + 1 > r0) ? -1e30f : c[nb][1] + t + slope2;
                    c[nb][2] = (col     > r1) ? -1e30f : c[nb][2] + t;
                    c[nb][3] = (col + 1 > r1) ? -1e30f : c[nb][3] + t + slope2;
                    mx0 = fmaxf(mx0, fmaxf(c[nb][0], c[nb][1]));
                    mx1 = fmaxf(mx1, fmaxf(c[nb][2], c[nb][3]));
                }
                mx0 = fmaxf(mx0, __shfl_xor_sync(0xffffffffu, mx0, 1));
                mx0 = fmaxf(mx0, __shfl_xor_sync(0xffffffffu, mx0, 2));
                mx1 = fmaxf(mx1, __shfl_xor_sync(0xffffffffu, mx1, 1));
                mx1 = fmaxf(mx1, __shfl_xor_sync(0xffffffffu, mx1, 2));
                m0 = mx0;
                m1 = mx1;
                #pragma unroll
                for (int nb = 0; nb < 8; nb++) {
                    uint32_t pa = pack_h2(c[nb][0] - m0, c[nb][1] - m0);
                    uint32_t pb = pack_h2(c[nb][2] - m1, c[nb][3] - m1);
                    ph[nb >> 1][(nb & 1) * 2]     = h2exp2(pa);
                    ph[nb >> 1][(nb & 1) * 2 + 1] = h2exp2(pb);
                }
            } else {
                // steady state: p = exp2(s + alibi - m^); no max, no rescale
                const float km0 = kadd - m0;
                const float km1 = kadd - m1;
                #pragma unroll
                for (int nb = 0; nb < 8; nb++) {
                    float t0 = a0[nb] + km0;
                    float t1 = a0[nb] + km1;
                    uint32_t pa = pack_h2(c[nb][0] + t0, c[nb][1] + t0 + slope2);
                    uint32_t pb = pack_h2(c[nb][2] + t1, c[nb][3] + t1 + slope2);
                    ph[nb >> 1][(nb & 1) * 2]     = h2exp2(pa);
                    ph[nb >> 1][(nb & 1) * 2 + 1] = h2exp2(pb);
                }
            }

            // l accumulation on the fma pipe (h2 per-tile partials -> fp32)
            {
                uint32_t s0 = 0u, s1 = 0u;
                #pragma unroll
                for (int q = 0; q < 4; q++) {
                    s0 = hadd2u(s0, ph[q][0]);
                    s0 = hadd2u(s0, ph[q][2]);
                    s1 = hadd2u(s1, ph[q][1]);
                    s1 = hadd2u(s1, ph[q][3]);
                }
                l0 += h2sum(s0);
                l1 += h2sum(s1);
            }

            // O += P . V
            #pragma unroll
            for (int kpi = 0; kpi < 4; kpi++) {
                #pragma unroll
                for (int np = 0; np < 4; np++) {
                    uint32_t vf[4];
                    int row = kpi * 16 + ((lane >> 3) & 1) * 8 + (lane & 7);
                    int cc = 2 * np + (lane >> 4);
                    LDSM4T(vf, bV + row * 128 + ((cc ^ (row & 7)) * 16));
                    mma16816(o[2 * np],     ph[kpi], vf[0], vf[1]);
                    mma16816(o[2 * np + 1], ph[kpi], vf[2], vf[3]);
                }
            }
            __syncthreads();
        }

        // finalize: reduce l across the row quad, then normalize + store
        l0 += __shfl_xor_sync(0xffffffffu, l0, 1);
        l0 += __shfl_xor_sync(0xffffffffu, l0, 2);
        l1 += __shfl_xor_sync(0xffffffffu, l1, 1);
        l1 += __shfl_xor_sync(0xffffffffu, l1, 2);
        const float inv0 = 1.f / l0;
        const float inv1 = 1.f / l1;
        #pragma unroll
        for (int nb = 0; nb < 8; nb++) {
            int colhd = nb * 8 + (lane & 3) * 2;
            size_t o0 = ((size_t)(bb * NN + r0)) * DD + h * HDIM + colhd;
            size_t o1 = ((size_t)(bb * NN + r1)) * DD + h * HDIM + colhd;
            *reinterpret_cast<__half2*>(g_ch + o0) =
                __floats2half2_rn(o[nb][0] * inv0, o[nb][1] * inv0);
            *reinterpret_cast<__half2*>(g_ch + o1) =
                __floats2half2_rn(o[nb][2] * inv1, o[nb][3] * inv1);
        }
        __syncthreads();   // smem safe for next phase
    }
    #undef LOAD_KV
}

// ---------------------------------------------------------------------------
extern "C" void kernel_launch(void* const* d_in, const int* in_sizes, int n_in,
                              void* d_out, int out_size)
{
    const float* x  = (const float*)d_in[0];
    const float* Wq = (const float*)d_in[1];
    const float* Wk = (const float*)d_in[2];
    const float* Wv = (const float*)d_in[3];
    const float* Wo = (const float*)d_in[4];
    const float* bo = (const float*)d_in[5];
    float* out = (float*)d_out;

    cudaFuncSetAttribute(gemm_hmma_kernel,
                         cudaFuncAttributeMaxDynamicSharedMemorySize, GEMM_SMEM);
    cudaFuncSetAttribute(attn_hmma_kernel,
                         cudaFuncAttributeMaxDynamicSharedMemorySize, ATTN_SMEM);

    __half *xh, *ch;
    cudaGetSymbolAddress((void**)&xh, g_xh);
    cudaGetSymbolAddress((void**)&ch, g_ch);

    convert_all_kernel<<<8192, 256>>>(x, Wq, Wk, Wv, Wo);

    // QKV projections
    gemm_hmma_kernel<<<dim3(8, 32, 3), 256, GEMM_SMEM>>>(xh, nullptr, nullptr, 0);

    // attention (balanced pairing, fixed-reference softmax)
    attn_hmma_kernel<<<dim3(16, HH, BB), 128, ATTN_SMEM>>>();

    // output projection
    gemm_hmma_kernel<<<dim3(8, 32, 1), 256, GEMM_SMEM>>>(ch, bo, out, 3);
}